// round 12
// baseline (speedup 1.0000x reference)
#include <cuda_runtime.h>
#include <cuda_fp16.h>
#include <cstdint>

// Problem dims
#define NL 16
#define DH 128
#define G4 512      // 4*H
#define BB 32
#define TT 512
#define NH 2048     // N*H
#define STRD 136    // padded halves per row (conflict-free LDS)
#define RPAD 516    // ring row pad (halves) -> bank-shift 2 words per b-row

// SMEM layout (bytes)
#define S_WS   0                       // W_ih fp16 [512][STRD] = 139264
#define S_HS   139264                  // h tiles  [2][8][STRD] halves = 4352
#define S_RING 143616                  // zx ring  [2][4 tl][4 b][RPAD] halves = 33024
#define S_XB   176640                  // x stage  [2][16][132] fp32 = 16896
#define S_TOTAL 193536

// ---------------- mma.sync m16n8k16 (fp16 in, fp32 acc) ----------------
__device__ __forceinline__ void mma16816(float* d, const uint32_t* a,
                                         uint32_t b0, uint32_t b1) {
    asm volatile("mma.sync.aligned.m16n8k16.row.col.f32.f16.f16.f32 "
                 "{%0,%1,%2,%3}, {%4,%5,%6,%7}, {%8,%9}, {%0,%1,%2,%3};"
                 : "+f"(d[0]), "+f"(d[1]), "+f"(d[2]), "+f"(d[3])
                 : "r"(a[0]), "r"(a[1]), "r"(a[2]), "r"(a[3]), "r"(b0), "r"(b1));
}

__device__ __forceinline__ float tanh_apx(float x) {
    float t;
    asm("tanh.approx.f32 %0, %1;" : "=f"(t) : "f"(x));
    return t;
}
__device__ __forceinline__ float sigm_apx(float x) {
    return fmaf(0.5f, tanh_apx(0.5f * x), 0.5f);
}
__device__ __forceinline__ uint32_t smem_u32(const void* p) {
    uint32_t a;
    asm("{ .reg .u64 t; cvta.to.shared.u64 t, %1; cvt.u32.u64 %0, t; }" : "=r"(a) : "l"(p));
    return a;
}

// =================================================================
// FUSED persistent WideLSTM. grid 128 = n(16) x bc(8 of 4 batches),
// 256 threads (8 warps).
// Consumer (R10 design): W_hh in regs, warp-local epilogue, batches
// in even mma N-cols, 1 barrier/step. zx read from SMEM ring.
// Producer (same warps, every 4 steps): zx_next = W_ih.x + bias
// from SMEM W_ih + cp.async-staged x, written to the ring.
// =================================================================
__global__ void __launch_bounds__(256, 1) wlstm_fused(
    const float* __restrict__ x, const float* __restrict__ Wih,
    const float* __restrict__ Whh, const float* __restrict__ bih,
    const float* __restrict__ bhh, float* __restrict__ out)
{
    extern __shared__ char smem[];
    __half*   ws   = (__half*)(smem + S_WS);
    __half*   hsb  = (__half*)(smem + S_HS);
    __half*   ring = (__half*)(smem + S_RING);
    float*    xb   = (float*)(smem + S_XB);
    const uint32_t xb_sm = smem_u32(smem) + S_XB;

    const int tid = threadIdx.x, wid = tid >> 5, lane = tid & 31;
    const int g0 = lane >> 2, cq = lane & 3;
    const int n = blockIdx.x >> 3, bc = blockIdx.x & 7;

    // ---- W_ih[n] fp32 -> fp16 SMEM [g][STRD]
    const float4* W4 = (const float4*)(Wih + (size_t)n * G4 * DH);
#pragma unroll 4
    for (int i = tid; i < G4 * DH / 4; i += 256) {
        float4 w = W4[i];
        int r = i >> 5, k = (i & 31) * 4;
        __half2 h01 = __floats2half2_rn(w.x, w.y);
        __half2 h23 = __floats2half2_rn(w.z, w.w);
        uint2 v = { *(uint32_t*)&h01, *(uint32_t*)&h23 };
        *(uint2*)(ws + r * STRD + k) = v;
    }
    // hs zero (odd N-col slots stay zero forever)
    for (int i = tid; i < 2 * 8 * STRD; i += 256) hsb[i] = __float2half(0.0f);

    // ---- W_hh[n] -> A-fragments (R10): gate gi tile rows gi*128 + wid*16
    uint32_t a[4][8][4];
    const float* W = Whh + (size_t)n * G4 * DH;
#pragma unroll
    for (int gi = 0; gi < 4; gi++) {
        int r0 = gi * 128 + wid * 16 + g0;
#pragma unroll
        for (int kc = 0; kc < 8; kc++) {
            int k0 = kc * 16 + cq * 2;
            float2 w00 = *(const float2*)(W + (size_t)r0 * DH + k0);
            float2 w10 = *(const float2*)(W + (size_t)(r0 + 8) * DH + k0);
            float2 w01 = *(const float2*)(W + (size_t)r0 * DH + k0 + 8);
            float2 w11 = *(const float2*)(W + (size_t)(r0 + 8) * DH + k0 + 8);
            __half2 h00 = __floats2half2_rn(w00.x, w00.y);
            __half2 h10 = __floats2half2_rn(w10.x, w10.y);
            __half2 h01 = __floats2half2_rn(w01.x, w01.y);
            __half2 h11 = __floats2half2_rn(w11.x, w11.y);
            a[gi][kc][0] = *(uint32_t*)&h00;
            a[gi][kc][1] = *(uint32_t*)&h10;
            a[gi][kc][2] = *(uint32_t*)&h01;
            a[gi][kc][3] = *(uint32_t*)&h11;
        }
    }

    // producer bias: rows gi*128 + wid*16 + g0 (+8)
    float bp[4][2];
#pragma unroll
    for (int gi = 0; gi < 4; gi++) {
        int r0 = gi * 128 + wid * 16 + g0;
        bp[gi][0] = bih[n * G4 + r0]     + bhh[n * G4 + r0];
        bp[gi][1] = bih[n * G4 + r0 + 8] + bhh[n * G4 + r0 + 8];
    }

    // consumer state mapping (R10)
    const int j0 = wid * 16 + g0;
    const int b  = bc * 4 + cq;
    float* ob[2];
    int hoff[2];
#pragma unroll
    for (int s = 0; s < 2; s++) {
        int j = j0 + s * 8;
        ob[s]  = out + (size_t)b * TT * NH + n * DH + j;
        hoff[s] = (2 * cq) * STRD + j;
    }
    float cst[2] = {0.0f, 0.0f}, hst[2] = {0.0f, 0.0f};

    const uint32_t* ws32 = (const uint32_t*)ws;

    // ---- cp.async x stage: block B (4 steps), buffer buf
    auto copy_x = [&](int B, int buf) {
        int r = tid >> 4;                 // 16 rows: r = tl*4 + bi
        int c8 = (tid & 15) * 8;          // 8 floats = 32B per thread
        const float* src = x + ((size_t)(bc * 4 + (r & 3)) * TT + (4 * B + (r >> 2))) * NH
                             + n * DH + c8;
        uint32_t dst = xb_sm + (uint32_t)(buf * (16 * 132) + r * 132 + c8) * 4;
        asm volatile("cp.async.cg.shared.global [%0], [%1], 16;" :: "r"(dst), "l"(src));
        asm volatile("cp.async.cg.shared.global [%0], [%1], 16;" :: "r"(dst + 16), "l"(src + 4));
        asm volatile("cp.async.commit_group;");
    };

    // ---- produce zx for block B into ring[B&1] from xb[B&1]
    auto produce = [&](int B) {
        const float* xs = xb + (B & 1) * (16 * 132);
        const int par = B & 1;
#pragma unroll
        for (int gi = 0; gi < 4; gi++) {
            int r0 = gi * 128 + wid * 16 + g0;
            float ac[2][4];
#pragma unroll
            for (int nt = 0; nt < 2; nt++)
#pragma unroll
                for (int q = 0; q < 4; q++) ac[nt][q] = 0.0f;
#pragma unroll
            for (int kc = 0; kc < 8; kc++) {
                uint32_t aa[4];
                int kw = kc * 8 + cq;
                aa[0] = ws32[r0 * (STRD / 2) + kw];
                aa[1] = ws32[(r0 + 8) * (STRD / 2) + kw];
                aa[2] = ws32[r0 * (STRD / 2) + kw + 4];
                aa[3] = ws32[(r0 + 8) * (STRD / 2) + kw + 4];
#pragma unroll
                for (int nt = 0; nt < 2; nt++) {
                    int col = nt * 8 + g0;
                    float2 lo = *(const float2*)(xs + col * 132 + kc * 16 + cq * 2);
                    float2 hi = *(const float2*)(xs + col * 132 + kc * 16 + cq * 2 + 8);
                    __half2 hl = __floats2half2_rn(lo.x, lo.y);
                    __half2 hh = __floats2half2_rn(hi.x, hi.y);
                    mma16816(ac[nt], aa, *(uint32_t*)&hl, *(uint32_t*)&hh);
                }
            }
#pragma unroll
            for (int nt = 0; nt < 2; nt++) {
                int c0 = nt * 8 + 2 * cq;
                int tl = c0 >> 2, bb = c0 & 3;
                int base = ((par * 4 + tl) * 4 + bb) * RPAD + (wid * 16 + g0) * 4 + gi;
                ring[base]             = __float2half(ac[nt][0] + bp[gi][0]);
                ring[base + RPAD]      = __float2half(ac[nt][1] + bp[gi][0]);
                ring[base + 32]        = __float2half(ac[nt][2] + bp[gi][1]);
                ring[base + RPAD + 32] = __float2half(ac[nt][3] + bp[gi][1]);
            }
        }
    };

    __syncthreads();                     // ws/hs visible

    // prologue: stage x for blocks 0,1; produce block 0
    copy_x(0, 0);
    copy_x(1, 1);
    asm volatile("cp.async.wait_group 0;" ::: "memory");
    __syncthreads();
    produce(0);
    __syncthreads();

    size_t toff = 0;

    for (int blk = 0; blk < 128; blk++) {
        if (blk < 127) {
            copy_x(blk + 2 <= 127 ? blk + 2 : 127, blk & 1);
            asm volatile("cp.async.wait_group 1;" ::: "memory");
            __syncthreads();             // x for block blk+1 visible to all
            produce(blk + 1);            // writes ring[(blk+1)&1]
        }
        const int rpar = (blk & 1) * 4;
#pragma unroll
        for (int tl2 = 0; tl2 < 4; tl2++) {
            int t = blk * 4 + tl2;
            // xp from ring (independent of mma — issue early)
            uint2 xp[2];
#pragma unroll
            for (int s = 0; s < 2; s++)
                xp[s] = *(const uint2*)(ring + ((rpar + tl2) * 4 + cq) * RPAD + (j0 + s * 8) * 4);

            // ---- z = W_hh . h_{t-1}
            const uint32_t* hb = (const uint32_t*)(hsb + (t & 1) * 8 * STRD);
            float d[4][4];
#pragma unroll
            for (int gi = 0; gi < 4; gi++)
#pragma unroll
                for (int q = 0; q < 4; q++) d[gi][q] = 0.0f;
#pragma unroll
            for (int kc = 0; kc < 8; kc++) {
                uint32_t b0 = hb[g0 * (STRD / 2) + kc * 8 + cq];
                uint32_t b1 = hb[g0 * (STRD / 2) + kc * 8 + cq + 4];
#pragma unroll
                for (int gi = 0; gi < 4; gi++) mma16816(d[gi], a[gi][kc], b0, b1);
            }

            // ---- warp-local epilogue: 2 states, all gates in-register
            __half* hw = hsb + ((t + 1) & 1) * 8 * STRD;
#pragma unroll
            for (int s = 0; s < 2; s++) {
                int q = s * 2;
                float2 f01 = __half22float2(*(__half2*)&xp[s].x);
                float2 f23 = __half22float2(*(__half2*)&xp[s].y);
                float zi = d[0][q] + f01.x;
                float zf = d[1][q] + f01.y;
                float zg = d[2][q] + f23.x;
                float zo = d[3][q] + f23.y;
                float ig = sigm_apx(zi);
                float fg = sigm_apx(zf);
                float gg = tanh_apx(zg);
                float og = sigm_apx(zo);
                float cv = fg * cst[s] + ig * gg;
                cst[s] = cv;
                float hv = og * tanh_apx(cv);
                hst[s] = hv;
                ob[s][toff] = hv;
                hw[hoff[s]] = __float2half(hv);
            }
            toff += NH;
            __syncthreads();             // h(t) + ring reads ordered
        }
    }

    // h_n, c_n: out = [output | h_n | c_n]
    float* hn = out + (size_t)BB * TT * NH;
    float* cn = hn + (size_t)BB * NH;
#pragma unroll
    for (int s = 0; s < 2; s++) {
        int j = j0 + s * 8;
        hn[(size_t)b * NH + n * DH + j] = hst[s];
        cn[(size_t)b * NH + n * DH + j] = cst[s];
    }
}

extern "C" void kernel_launch(void* const* d_in, const int* in_sizes, int n_in,
                              void* d_out, int out_size) {
    const float* x   = (const float*)d_in[0];
    const float* Wih = (const float*)d_in[1];
    const float* Whh = (const float*)d_in[2];
    const float* bih = (const float*)d_in[3];
    const float* bhh = (const float*)d_in[4];
    float* out = (float*)d_out;

    cudaFuncSetAttribute(wlstm_fused,
                         cudaFuncAttributeMaxDynamicSharedMemorySize, S_TOTAL);

    wlstm_fused<<<NL * 8, 256, S_TOTAL>>>(x, Wih, Whh, bih, bhh, out);
}

// round 13
// speedup vs baseline: 1.1346x; 1.1346x over previous
#include <cuda_runtime.h>
#include <cuda_fp16.h>
#include <cstdint>

// Problem dims
#define NL 16
#define DH 128
#define G4 512      // 4*H
#define BB 32
#define TT 512
#define NH 2048     // N*H
#define STRD 136    // padded halves per row (conflict-free LDS)
#define RPAD 516    // ring row pad (halves)

// SMEM layout (bytes)
#define S_WS   0                       // W_ih fp16 [512][STRD] = 139264
#define S_HS   139264                  // h tiles  [2][8][STRD] = 4352
#define S_RING 143616                  // zx ring  [2 slot][4 tl][4 b][RPAD] = 33024
#define S_XB   176640                  // x stage  [2][16][132] fp32 = 16896
#define S_MB   193536                  // mbarriers: full0 full1 empty0 empty1
#define S_TOTAL 193600

// ---------------- mma.sync m16n8k16 (fp16 in, fp32 acc) ----------------
__device__ __forceinline__ void mma16816(float* d, const uint32_t* a,
                                         uint32_t b0, uint32_t b1) {
    asm volatile("mma.sync.aligned.m16n8k16.row.col.f32.f16.f16.f32 "
                 "{%0,%1,%2,%3}, {%4,%5,%6,%7}, {%8,%9}, {%0,%1,%2,%3};"
                 : "+f"(d[0]), "+f"(d[1]), "+f"(d[2]), "+f"(d[3])
                 : "r"(a[0]), "r"(a[1]), "r"(a[2]), "r"(a[3]), "r"(b0), "r"(b1));
}

__device__ __forceinline__ float tanh_apx(float x) {
    float t;
    asm("tanh.approx.f32 %0, %1;" : "=f"(t) : "f"(x));
    return t;
}
__device__ __forceinline__ float sigm_apx(float x) {
    return fmaf(0.5f, tanh_apx(0.5f * x), 0.5f);
}
__device__ __forceinline__ uint32_t smem_u32(const void* p) {
    uint32_t a;
    asm("{ .reg .u64 t; cvta.to.shared.u64 t, %1; cvt.u32.u64 %0, t; }" : "=r"(a) : "l"(p));
    return a;
}

#define MBAR_INIT(addr, cnt) \
    asm volatile("mbarrier.init.shared.b64 [%0], %1;" :: "r"(addr), "r"(cnt) : "memory")
#define MBAR_ARRIVE(addr) \
    asm volatile("mbarrier.arrive.shared.b64 _, [%0];" :: "r"(addr) : "memory")

__device__ __forceinline__ void mbar_wait(uint32_t mbar, uint32_t parity) {
    uint32_t done;
    asm volatile("{\n\t.reg .pred p;\n\t"
                 "mbarrier.try_wait.parity.shared.b64 p, [%1], %2;\n\t"
                 "selp.b32 %0, 1, 0, p;\n\t}"
                 : "=r"(done) : "r"(mbar), "r"(parity) : "memory");
    if (!done) {
        asm volatile("{\n\t.reg .pred P1;\n\t"
                     "WL_%=:\n\t"
                     "mbarrier.try_wait.parity.shared.b64 P1, [%0], %1, 0x989680;\n\t"
                     "@P1 bra.uni WD_%=;\n\t"
                     "bra.uni WL_%=;\n\t"
                     "WD_%=:\n\t}"
                     :: "r"(mbar), "r"(parity) : "memory");
    }
}

// =================================================================
// WARP-SPECIALIZED fused WideLSTM. grid 128 = n(16) x bc(8),
// 384 threads: warps 0-7 consumer (R10 recurrence), warps 8-11
// producer (W_ih.x + bias -> SMEM ring, cp.async x staging).
// =================================================================
__global__ void __launch_bounds__(384, 1) wlstm_ws(
    const float* __restrict__ x, const float* __restrict__ Wih,
    const float* __restrict__ Whh, const float* __restrict__ bih,
    const float* __restrict__ bhh, float* __restrict__ out)
{
    extern __shared__ char smem[];
    __half*   ws   = (__half*)(smem + S_WS);
    __half*   hsb  = (__half*)(smem + S_HS);
    __half*   ring = (__half*)(smem + S_RING);
    float*    xb   = (float*)(smem + S_XB);
    const uint32_t sbase = smem_u32(smem);
    const uint32_t mb_full0  = sbase + S_MB;
    const uint32_t mb_full1  = sbase + S_MB + 8;
    const uint32_t mb_empty0 = sbase + S_MB + 16;
    const uint32_t mb_empty1 = sbase + S_MB + 24;
    const uint32_t xb_sm = sbase + S_XB;

    const int tid = threadIdx.x, wid = tid >> 5, lane = tid & 31;
    const int g0 = lane >> 2, cq = lane & 3;
    const int n = blockIdx.x >> 3, bc = blockIdx.x & 7;

    // ---- common init: W_ih -> SMEM fp16, hs zero, mbarriers
    const float4* W4 = (const float4*)(Wih + (size_t)n * G4 * DH);
#pragma unroll 4
    for (int i = tid; i < G4 * DH / 4; i += 384) {
        float4 w = W4[i];
        int r = i >> 5, k = (i & 31) * 4;
        __half2 h01 = __floats2half2_rn(w.x, w.y);
        __half2 h23 = __floats2half2_rn(w.z, w.w);
        uint2 v = { *(uint32_t*)&h01, *(uint32_t*)&h23 };
        *(uint2*)(ws + r * STRD + k) = v;
    }
    for (int i = tid; i < 2 * 8 * STRD; i += 384) hsb[i] = __float2half(0.0f);
    if (tid == 0) {
        MBAR_INIT(mb_full0, 128);  MBAR_INIT(mb_full1, 128);
        MBAR_INIT(mb_empty0, 256); MBAR_INIT(mb_empty1, 256);
    }
    __syncthreads();   // last block-wide barrier; roles diverge below

    if (wid < 8) {
        // ============================ CONSUMER ============================
        uint32_t a[4][8][4];
        const float* W = Whh + (size_t)n * G4 * DH;
#pragma unroll
        for (int gi = 0; gi < 4; gi++) {
            int r0 = gi * 128 + wid * 16 + g0;
#pragma unroll
            for (int kc = 0; kc < 8; kc++) {
                int k0 = kc * 16 + cq * 2;
                float2 w00 = *(const float2*)(W + (size_t)r0 * DH + k0);
                float2 w10 = *(const float2*)(W + (size_t)(r0 + 8) * DH + k0);
                float2 w01 = *(const float2*)(W + (size_t)r0 * DH + k0 + 8);
                float2 w11 = *(const float2*)(W + (size_t)(r0 + 8) * DH + k0 + 8);
                __half2 h00 = __floats2half2_rn(w00.x, w00.y);
                __half2 h10 = __floats2half2_rn(w10.x, w10.y);
                __half2 h01 = __floats2half2_rn(w01.x, w01.y);
                __half2 h11 = __floats2half2_rn(w11.x, w11.y);
                a[gi][kc][0] = *(uint32_t*)&h00;
                a[gi][kc][1] = *(uint32_t*)&h10;
                a[gi][kc][2] = *(uint32_t*)&h01;
                a[gi][kc][3] = *(uint32_t*)&h11;
            }
        }
        const int j0 = wid * 16 + g0;
        const int b  = bc * 4 + cq;
        float* ob[2];
        int hoff[2];
#pragma unroll
        for (int s = 0; s < 2; s++) {
            int j = j0 + s * 8;
            ob[s]  = out + (size_t)b * TT * NH + n * DH + j;
            hoff[s] = (2 * cq) * STRD + j;
        }
        float cst[2] = {0.0f, 0.0f}, hst[2] = {0.0f, 0.0f};
        size_t toff = 0;

        for (int blk = 0; blk < 128; blk++) {
            const int sl = blk & 1;
            mbar_wait(sl ? mb_full1 : mb_full0, (blk >> 1) & 1);
#pragma unroll
            for (int tl2 = 0; tl2 < 4; tl2++) {
                int t = blk * 4 + tl2;
                uint2 xp[2];
#pragma unroll
                for (int s = 0; s < 2; s++)
                    xp[s] = *(const uint2*)(ring + ((sl * 4 + tl2) * 4 + cq) * RPAD
                                            + (j0 + s * 8) * 4);
                const uint32_t* hb = (const uint32_t*)(hsb + (t & 1) * 8 * STRD);
                float d[4][4];
#pragma unroll
                for (int gi = 0; gi < 4; gi++)
#pragma unroll
                    for (int q = 0; q < 4; q++) d[gi][q] = 0.0f;
#pragma unroll
                for (int kc = 0; kc < 8; kc++) {
                    uint32_t b0 = hb[g0 * (STRD / 2) + kc * 8 + cq];
                    uint32_t b1 = hb[g0 * (STRD / 2) + kc * 8 + cq + 4];
#pragma unroll
                    for (int gi = 0; gi < 4; gi++) mma16816(d[gi], a[gi][kc], b0, b1);
                }
                __half* hw = hsb + ((t + 1) & 1) * 8 * STRD;
#pragma unroll
                for (int s = 0; s < 2; s++) {
                    int q = s * 2;
                    float2 f01 = __half22float2(*(__half2*)&xp[s].x);
                    float2 f23 = __half22float2(*(__half2*)&xp[s].y);
                    float zi = d[0][q] + f01.x;
                    float zf = d[1][q] + f01.y;
                    float zg = d[2][q] + f23.x;
                    float zo = d[3][q] + f23.y;
                    float ig = sigm_apx(zi);
                    float fg = sigm_apx(zf);
                    float gg = tanh_apx(zg);
                    float og = sigm_apx(zo);
                    float cv = fg * cst[s] + ig * gg;
                    cst[s] = cv;
                    float hv = og * tanh_apx(cv);
                    hst[s] = hv;
                    ob[s][toff] = hv;
                    hw[hoff[s]] = __float2half(hv);
                }
                toff += NH;
                asm volatile("bar.sync 1, 256;" ::: "memory");
            }
            MBAR_ARRIVE(sl ? mb_empty1 : mb_empty0);
        }

        float* hn = out + (size_t)BB * TT * NH;
        float* cn = hn + (size_t)BB * NH;
#pragma unroll
        for (int s = 0; s < 2; s++) {
            int j = j0 + s * 8;
            hn[(size_t)b * NH + n * DH + j] = hst[s];
            cn[(size_t)b * NH + n * DH + j] = cst[s];
        }
    } else {
        // ============================ PRODUCER ============================
        const int pw = wid - 8;             // 0..3 -> owns gate pw
        const int ptid = tid - 256;         // 0..127

        // bias for tiles k: rows pw*128 + k*16 + g0 (+8)
        float bp[8][2];
#pragma unroll
        for (int k = 0; k < 8; k++) {
            int r0 = pw * 128 + k * 16 + g0;
            bp[k][0] = bih[n * G4 + r0]     + bhh[n * G4 + r0];
            bp[k][1] = bih[n * G4 + r0 + 8] + bhh[n * G4 + r0 + 8];
        }

        auto copy_x = [&](int B, int buf) {
            int r = ptid >> 3;              // 16 rows: r = tl*4 + bi
            int c0 = (ptid & 7) * 16;       // 16 floats per thread
            const float* src = x + ((size_t)(bc * 4 + (r & 3)) * TT
                                    + (4 * B + (r >> 2))) * NH + n * DH + c0;
            uint32_t dst = xb_sm + (uint32_t)(buf * (16 * 132) + r * 132 + c0) * 4;
#pragma unroll
            for (int q = 0; q < 4; q++)
                asm volatile("cp.async.cg.shared.global [%0], [%1], 16;"
                             :: "r"(dst + q * 16), "l"(src + q * 4));
        };

        const uint32_t* ws32 = (const uint32_t*)ws;

        // prologue: stage blocks 0,1
        copy_x(0, 0); asm volatile("cp.async.commit_group;");
        copy_x(1, 1); asm volatile("cp.async.commit_group;");

        for (int B = 0; B < 128; B++) {
            const int sl = B & 1;
            asm volatile("cp.async.wait_group 1;" ::: "memory");
            asm volatile("bar.sync 2, 128;" ::: "memory");   // xb[sl] visible to all producers
            mbar_wait(sl ? mb_empty1 : mb_empty0, ((B >> 1) & 1) ^ 1);

            const float* xs = xb + sl * (16 * 132);
#pragma unroll
            for (int k = 0; k < 8; k++) {
                int r0 = pw * 128 + k * 16 + g0;
                // A-frags from SMEM W_ih
                uint32_t aa[8][4];
#pragma unroll
                for (int kc = 0; kc < 8; kc++) {
                    int kw = kc * 8 + cq;
                    aa[kc][0] = ws32[r0 * (STRD / 2) + kw];
                    aa[kc][1] = ws32[(r0 + 8) * (STRD / 2) + kw];
                    aa[kc][2] = ws32[r0 * (STRD / 2) + kw + 4];
                    aa[kc][3] = ws32[(r0 + 8) * (STRD / 2) + kw + 4];
                }
                float ac[2][4];
#pragma unroll
                for (int nt = 0; nt < 2; nt++)
#pragma unroll
                    for (int q = 0; q < 4; q++) ac[nt][q] = 0.0f;
#pragma unroll
                for (int kc = 0; kc < 8; kc++) {
#pragma unroll
                    for (int nt = 0; nt < 2; nt++) {
                        int col = nt * 8 + g0;
                        float2 lo = *(const float2*)(xs + col * 132 + kc * 16 + cq * 2);
                        float2 hi = *(const float2*)(xs + col * 132 + kc * 16 + cq * 2 + 8);
                        __half2 hl = __floats2half2_rn(lo.x, lo.y);
                        __half2 hh = __floats2half2_rn(hi.x, hi.y);
                        mma16816(ac[nt], aa[kc], *(uint32_t*)&hl, *(uint32_t*)&hh);
                    }
                }
#pragma unroll
                for (int nt = 0; nt < 2; nt++) {
                    int c0 = nt * 8 + 2 * cq;
                    int tl = c0 >> 2, bb = c0 & 3;
                    int base = ((sl * 4 + tl) * 4 + bb) * RPAD + (k * 16 + g0) * 4 + pw;
                    ring[base]             = __float2half(ac[nt][0] + bp[k][0]);
                    ring[base + RPAD]      = __float2half(ac[nt][1] + bp[k][0]);
                    ring[base + 32]        = __float2half(ac[nt][2] + bp[k][1]);
                    ring[base + RPAD + 32] = __float2half(ac[nt][3] + bp[k][1]);
                }
            }
            MBAR_ARRIVE(sl ? mb_full1 : mb_full0);
            asm volatile("bar.sync 2, 128;" ::: "memory");   // xb reads done before refill
            if (B + 2 < 128) copy_x(B + 2, sl);
            asm volatile("cp.async.commit_group;");          // keep group count uniform
        }
    }
}

extern "C" void kernel_launch(void* const* d_in, const int* in_sizes, int n_in,
                              void* d_out, int out_size) {
    const float* x   = (const float*)d_in[0];
    const float* Wih = (const float*)d_in[1];
    const float* Whh = (const float*)d_in[2];
    const float* bih = (const float*)d_in[3];
    const float* bhh = (const float*)d_in[4];
    float* out = (float*)d_out;

    cudaFuncSetAttribute(wlstm_ws,
                         cudaFuncAttributeMaxDynamicSharedMemorySize, S_TOTAL);

    wlstm_ws<<<NL * 8, 384, S_TOTAL>>>(x, Wih, Whh, bih, bhh, out);
}

// round 14
// speedup vs baseline: 1.3707x; 1.2080x over previous
#include <cuda_runtime.h>
#include <cuda_fp16.h>
#include <cstdint>

// Problem dims
#define NL 16
#define DH 128
#define G4 512      // 4*H
#define BB 32
#define TT 512
#define NH 2048     // N*H
#define STRD 136    // padded halves per row (conflict-free LDS)

// x_proj scratch, GATE-INTERLEAVED: [n][t][b][j][gate] fp16, bias pre-added
__device__ __half g_xp16[(size_t)NL * TT * BB * G4];

// ---------------- mma.sync m16n8k16 (fp16 in, fp32 acc) ----------------
__device__ __forceinline__ void mma16816(float* d, const uint32_t* a,
                                         uint32_t b0, uint32_t b1) {
    asm volatile("mma.sync.aligned.m16n8k16.row.col.f32.f16.f16.f32 "
                 "{%0,%1,%2,%3}, {%4,%5,%6,%7}, {%8,%9}, {%0,%1,%2,%3};"
                 : "+f"(d[0]), "+f"(d[1]), "+f"(d[2]), "+f"(d[3])
                 : "r"(a[0]), "r"(a[1]), "r"(a[2]), "r"(a[3]), "r"(b0), "r"(b1));
}

// HW tanh (1 MUFU); sigma(x) = 0.5*tanh(x/2)+0.5
__device__ __forceinline__ float tanh_apx(float x) {
    float t;
    asm("tanh.approx.f32 %0, %1;" : "=f"(t) : "f"(x));
    return t;
}
__device__ __forceinline__ float sigm_apx(float x) {
    return fmaf(0.5f, tanh_apx(0.5f * x), 0.5f);
}

// =================================================================
// Phase 1: x_proj16[n][t][b][j][g] = W_ih[n].x + b_ih + b_hh
// grid (8 hb, 16 n) = 128 CTAs (1 wave), 512 threads.
// Split accumulator chains (depth 4) — xproj has reg headroom.
// =================================================================
#define P1_TB 128
#define STGW 264
#define P1_S_WS  0
#define P1_S_X0  (G4 * STRD * 2)
#define P1_S_X1  (P1_S_X0 + P1_TB * STRD * 2)
#define P1_S_STG (P1_S_X1 + P1_TB * STRD * 2)
#define P1_SMEM  (P1_S_STG + 2 * 8 * STGW * 4)

__global__ void __launch_bounds__(512, 1) wlstm_xproj(
    const float* __restrict__ x, const float* __restrict__ Wih,
    const float* __restrict__ bih, const float* __restrict__ bhh)
{
    extern __shared__ char p1smem[];
    __half*    ws  = (__half*)(p1smem + P1_S_WS);
    __half*    xb0 = (__half*)(p1smem + P1_S_X0);
    __half*    xb1 = (__half*)(p1smem + P1_S_X1);
    uint32_t*  stw = (uint32_t*)(p1smem + P1_S_STG);

    const int tid = threadIdx.x, wid = tid >> 5, lane = tid & 31;
    const int g0 = lane >> 2, cq = lane & 3;
    const int n = blockIdx.y, hb = blockIdx.x;

    const float4* W4 = (const float4*)(Wih + (size_t)n * G4 * DH);
#pragma unroll 8
    for (int i = tid; i < G4 * DH / 4; i += 512) {
        float4 w = W4[i];
        int r = i >> 5, k = (i & 31) * 4;
        __half2 h01 = __floats2half2_rn(w.x, w.y);
        __half2 h23 = __floats2half2_rn(w.z, w.w);
        uint2 v = { *(uint32_t*)&h01, *(uint32_t*)&h23 };
        *(uint2*)(ws + r * STRD + k) = v;
    }

    auto load_tile = [&](int u, __half* dst) {
        int b = hb * 4 + (u >> 2), t0 = (u & 3) * P1_TB;
#pragma unroll 4
        for (int i = tid; i < P1_TB * DH / 4; i += 512) {
            int tl = i >> 5, c4 = (i & 31) * 4;
            float4 w = *(const float4*)(x + ((size_t)b * TT + t0 + tl) * NH + n * DH + c4);
            __half2 h01 = __floats2half2_rn(w.x, w.y);
            __half2 h23 = __floats2half2_rn(w.z, w.w);
            uint2 v = { *(uint32_t*)&h01, *(uint32_t*)&h23 };
            *(uint2*)(dst + tl * STRD + c4) = v;
        }
    };
    load_tile(0, xb0);
    __syncthreads();

    uint32_t a[2][8][4];
    const uint32_t* ws32 = (const uint32_t*)ws;
#pragma unroll
    for (int ti = 0; ti < 2; ti++) {
        int r0 = (2 * wid + ti) * 16 + g0;
#pragma unroll
        for (int kc = 0; kc < 8; kc++) {
            int kw = kc * 8 + cq;
            a[ti][kc][0] = ws32[r0 * (STRD / 2) + kw];
            a[ti][kc][1] = ws32[(r0 + 8) * (STRD / 2) + kw];
            a[ti][kc][2] = ws32[r0 * (STRD / 2) + kw + 4];
            a[ti][kc][3] = ws32[(r0 + 8) * (STRD / 2) + kw + 4];
        }
    }
    float bsv[2][2];
#pragma unroll
    for (int ti = 0; ti < 2; ti++) {
        int r0 = (2 * wid + ti) * 16 + g0;
        bsv[ti][0] = bih[n * G4 + r0]     + bhh[n * G4 + r0];
        bsv[ti][1] = bih[n * G4 + r0 + 8] + bhh[n * G4 + r0 + 8];
    }

    for (int u = 0; u < 16; u++) {
        const __half* xs = (u & 1) ? xb1 : xb0;
        if (u < 15) load_tile(u + 1, (u & 1) ? xb0 : xb1);

        int b = hb * 4 + (u >> 2), t0 = (u & 3) * P1_TB;
        __half* ob = g_xp16 + ((size_t)(n * TT + t0) * BB + b) * G4;
        const uint32_t* xs32 = (const uint32_t*)xs;

        for (int nt = 0; nt < 16; nt++) {
            uint32_t* stg = stw + (nt & 1) * (8 * STGW);
            __half*   sth = (__half*)stg;
            // split accumulator chains: even/odd kc (depth 8 -> 4)
            float dA[2][4], dB[2][4];
#pragma unroll
            for (int ti = 0; ti < 2; ti++)
#pragma unroll
                for (int q = 0; q < 4; q++) { dA[ti][q] = 0.0f; dB[ti][q] = 0.0f; }

            int col = nt * 8 + g0;
#pragma unroll
            for (int kc = 0; kc < 8; kc += 2) {
                uint32_t b0 = xs32[col * (STRD / 2) + kc * 8 + cq];
                uint32_t b1 = xs32[col * (STRD / 2) + kc * 8 + cq + 4];
                uint32_t c0 = xs32[col * (STRD / 2) + (kc + 1) * 8 + cq];
                uint32_t c1 = xs32[col * (STRD / 2) + (kc + 1) * 8 + cq + 4];
#pragma unroll
                for (int ti = 0; ti < 2; ti++) mma16816(dA[ti], a[ti][kc], b0, b1);
#pragma unroll
                for (int ti = 0; ti < 2; ti++) mma16816(dB[ti], a[ti][kc + 1], c0, c1);
            }
            int tb0 = 2 * cq;
#pragma unroll
            for (int ti = 0; ti < 2; ti++) {
                int r0 = (2 * wid + ti) * 16 + g0;
                int j = r0 & 127, gate = r0 >> 7;
                sth[(size_t)tb0 * (2 * STGW) + j * 4 + gate]             = __float2half(dA[ti][0] + dB[ti][0] + bsv[ti][0]);
                sth[(size_t)(tb0 + 1) * (2 * STGW) + j * 4 + gate]       = __float2half(dA[ti][1] + dB[ti][1] + bsv[ti][0]);
                sth[(size_t)tb0 * (2 * STGW) + (j + 8) * 4 + gate]       = __float2half(dA[ti][2] + dB[ti][2] + bsv[ti][1]);
                sth[(size_t)(tb0 + 1) * (2 * STGW) + (j + 8) * 4 + gate] = __float2half(dA[ti][3] + dB[ti][3] + bsv[ti][1]);
            }
            __syncthreads();
            {
                int tl = tid >> 6, w4 = tid & 63;
                uint4 v = *(const uint4*)(stg + tl * STGW + w4 * 4);
                *(uint4*)(ob + (size_t)(nt * 8 + tl) * (BB * G4) + w4 * 8) = v;
            }
        }
        __syncthreads();
    }
}

// =================================================================
// Phase 2: persistent recurrence — EXACT R10 (best measured).
// grid 128 = n(16) x bc(8 of 4 batches), 256 threads (8 warps).
// Batches in EVEN mma N-cols; warp-local epilogue; 1 barrier/step.
// =================================================================
__global__ void __launch_bounds__(256, 1) wlstm_rec(
    const float* __restrict__ Whh, float* __restrict__ out)
{
    __shared__ __half hs[2][8][STRD];   // [buf][N-col slot][j]; odd slots = 0 pad

    const int tid = threadIdx.x, wid = tid >> 5, lane = tid & 31;
    const int g0 = lane >> 2, cq = lane & 3;
    const int n = blockIdx.x >> 3, bc = blockIdx.x & 7;

    for (int i = tid; i < 2 * 8 * STRD; i += 256) ((__half*)hs)[i] = __float2half(0.0f);

    // ---- W_hh[n] -> A-fragments: gate gi tile rows gi*128 + wid*16
    uint32_t a[4][8][4];
    const float* W = Whh + (size_t)n * G4 * DH;
#pragma unroll
    for (int gi = 0; gi < 4; gi++) {
        int r0 = gi * 128 + wid * 16 + g0;
#pragma unroll
        for (int kc = 0; kc < 8; kc++) {
            int k0 = kc * 16 + cq * 2;
            float2 w00 = *(const float2*)(W + (size_t)r0 * DH + k0);
            float2 w10 = *(const float2*)(W + (size_t)(r0 + 8) * DH + k0);
            float2 w01 = *(const float2*)(W + (size_t)r0 * DH + k0 + 8);
            float2 w11 = *(const float2*)(W + (size_t)(r0 + 8) * DH + k0 + 8);
            __half2 h00 = __floats2half2_rn(w00.x, w00.y);
            __half2 h10 = __floats2half2_rn(w10.x, w10.y);
            __half2 h01 = __floats2half2_rn(w01.x, w01.y);
            __half2 h11 = __floats2half2_rn(w11.x, w11.y);
            a[gi][kc][0] = *(uint32_t*)&h00;
            a[gi][kc][1] = *(uint32_t*)&h10;
            a[gi][kc][2] = *(uint32_t*)&h01;
            a[gi][kc][3] = *(uint32_t*)&h11;
        }
    }

    const int j0 = wid * 16 + g0;
    const int b  = bc * 4 + cq;

    const __half* xqb[2];
    float* ob[2];
    int hoff[2];
#pragma unroll
    for (int s = 0; s < 2; s++) {
        int j = j0 + s * 8;
        xqb[s] = g_xp16 + ((size_t)n * TT * BB + b) * G4 + j * 4;
        ob[s]  = out + (size_t)b * TT * NH + n * DH + j;
        hoff[s] = (2 * cq) * STRD + j;
    }

    uint2 xpa[2], xpb[2];
#pragma unroll
    for (int s = 0; s < 2; s++) xpa[s] = *(const uint2*)xqb[s];

    float cst[2] = {0.0f, 0.0f}, hst[2] = {0.0f, 0.0f};

    __syncthreads();

    size_t toff = 0;

    auto step = [&](int t, uint2 (&xpc)[2], uint2 (&xpn)[2]) {
        if (t + 1 < TT) {
            size_t xo = (size_t)(t + 1) * (BB * G4);
#pragma unroll
            for (int s = 0; s < 2; s++) xpn[s] = *(const uint2*)(xqb[s] + xo);
        }
        const uint32_t* hb = (const uint32_t*)hs[t & 1];
        float d[4][4];
#pragma unroll
        for (int gi = 0; gi < 4; gi++)
#pragma unroll
            for (int q = 0; q < 4; q++) d[gi][q] = 0.0f;
#pragma unroll
        for (int kc = 0; kc < 8; kc++) {
            uint32_t b0 = hb[g0 * (STRD / 2) + kc * 8 + cq];
            uint32_t b1 = hb[g0 * (STRD / 2) + kc * 8 + cq + 4];
#pragma unroll
            for (int gi = 0; gi < 4; gi++) mma16816(d[gi], a[gi][kc], b0, b1);
        }

        __half* hw = (__half*)hs[(t + 1) & 1];
#pragma unroll
        for (int s = 0; s < 2; s++) {
            int q = s * 2;
            float2 f01 = __half22float2(*(__half2*)&xpc[s].x);
            float2 f23 = __half22float2(*(__half2*)&xpc[s].y);
            float zi = d[0][q] + f01.x;
            float zf = d[1][q] + f01.y;
            float zg = d[2][q] + f23.x;
            float zo = d[3][q] + f23.y;
            float ig = sigm_apx(zi);
            float fg = sigm_apx(zf);
            float gg = tanh_apx(zg);
            float og = sigm_apx(zo);
            float cv = fg * cst[s] + ig * gg;
            cst[s] = cv;
            float hv = og * tanh_apx(cv);
            hst[s] = hv;
            ob[s][toff] = hv;
            hw[hoff[s]] = __float2half(hv);
        }
        toff += NH;
        __syncthreads();
    };

    for (int t = 0; t < TT; t += 2) {
        step(t, xpa, xpb);
        step(t + 1, xpb, xpa);
    }

    float* hn = out + (size_t)BB * TT * NH;
    float* cn = hn + (size_t)BB * NH;
#pragma unroll
    for (int s = 0; s < 2; s++) {
        int j = j0 + s * 8;
        hn[(size_t)b * NH + n * DH + j] = hst[s];
        cn[(size_t)b * NH + n * DH + j] = cst[s];
    }
}

extern "C" void kernel_launch(void* const* d_in, const int* in_sizes, int n_in,
                              void* d_out, int out_size) {
    const float* x   = (const float*)d_in[0];
    const float* Wih = (const float*)d_in[1];
    const float* Whh = (const float*)d_in[2];
    const float* bih = (const float*)d_in[3];
    const float* bhh = (const float*)d_in[4];
    float* out = (float*)d_out;

    cudaFuncSetAttribute(wlstm_xproj,
                         cudaFuncAttributeMaxDynamicSharedMemorySize, P1_SMEM);

    dim3 g1(8, NL);   // 128 CTAs, 1 wave
    wlstm_xproj<<<g1, 512, P1_SMEM>>>(x, Wih, bih, bhh);
    wlstm_rec<<<NL * 8, 256>>>(Whh, out);
}